// round 2
// baseline (speedup 1.0000x reference)
#include <cuda_runtime.h>
#include <math.h>
#include <stdint.h>

#define NLVL 16
#define MAX_ENTRY (1u << 19)
#define HASH_MASK (MAX_ENTRY - 1u)

// Per-level parameters, computed on device to bit-match numpy's double math.
struct LvlP {
    float scale;   // res - 1.0
    float cap;     // (float)(res - 1.0001)
    int   res;
    int   res2;
    int   dense;   // 1 if res^3 < 2^19
};

__device__ LvlP g_lvl[NLVL];

__global__ void init_lvl_kernel() {
    int l = threadIdx.x;
    if (l < NLVL) {
        double step = (log(2048.0) - log(16.0)) / 15.0;
        double b = exp(step);
        double r = floor(16.0 * pow(b, (double)l));
        LvlP p;
        int res = (int)r;
        p.scale = (float)(r - 1.0);
        p.cap   = (float)(r - 1.0001);
        p.res   = res;
        p.res2  = res * res;
        p.dense = ((r * r * r) < (double)MAX_ENTRY) ? 1 : 0;
        g_lvl[l] = p;
    }
}

// ---------------------------------------------------------------------------
// Main kernel: levels 3..15 (dense 3-5 with float4 pairing, hashed 6-15).
// Stages 32-float rows in smem (cols 0..5 zeroed) and does coalesced
// cooperative stores: 1 wavefront per point instead of 8.
// ---------------------------------------------------------------------------
__global__ __launch_bounds__(256)
void grid_main_kernel(const float* __restrict__ x,
                      const float* __restrict__ tables,
                      float* __restrict__ out,
                      int n)
{
    __shared__ float srow[256 * 33];   // 33-float stride: conflict-free
    int tid = threadIdx.x;
    int i = blockIdx.x * 256 + tid;
    int isafe = (i < n) ? i : 0;

    float px = __ldg(&x[3 * isafe + 0]);
    float py = __ldg(&x[3 * isafe + 1]);
    float pz = __ldg(&x[3 * isafe + 2]);

    const float2* __restrict__ tbl = (const float2*)tables;
    float* my = srow + tid * 33;
    my[0] = my[1] = my[2] = my[3] = my[4] = my[5] = 0.0f;   // cols 0..5: other kernels

#pragma unroll 1
    for (int l = 3; l < NLVL; ++l) {
        LvlP p = g_lvl[l];

        float cx = fminf(fmaxf(px * p.scale, 0.0f), p.cap);
        float cy = fminf(fmaxf(py * p.scale, 0.0f), p.cap);
        float cz = fminf(fmaxf(pz * p.scale, 0.0f), p.cap);
        float fx = floorf(cx), fy = floorf(cy), fz = floorf(cz);
        int ix = (int)fx, iy = (int)fy, iz = (int)fz;

        float xw = cx - fx, yw = cy - fy, zw = cz - fz;
        float mxw = 1.0f - xw, myw = 1.0f - yw, mzw = 1.0f - zw;

        const float2* __restrict__ t = tbl + (size_t)l * MAX_ENTRY;
        float accx = 0.0f, accy = 0.0f;

        if (p.dense) {
            unsigned int base = (unsigned int)(ix + iy * p.res + iz * p.res2);
            unsigned int dr = (unsigned int)p.res;
            unsigned int dr2 = (unsigned int)p.res2;
            unsigned int offs[4] = {0u, dr2, dr, dr + dr2};
            float wyz[4] = {myw * mzw, myw * zw, yw * mzw, yw * zw};
#pragma unroll
            for (int r = 0; r < 4; ++r) {
                unsigned int u = base + offs[r];
                float2 e0, e1;
                if (!(u & 1u)) {
                    float4 q = __ldg(&((const float4*)t)[u >> 1]);
                    e0 = make_float2(q.x, q.y);
                    e1 = make_float2(q.z, q.w);
                } else {
                    e0 = __ldg(&t[u]);
                    e1 = __ldg(&t[u + 1]);
                }
                float w0 = wyz[r] * mxw, w1 = wyz[r] * xw;
                accx = fmaf(w0, e0.x, fmaf(w1, e1.x, accx));
                accy = fmaf(w0, e0.y, fmaf(w1, e1.y, accy));
            }
        } else {
            unsigned int h0a = (unsigned int)ix * 3367900313u;
            unsigned int h0b = (unsigned int)(ix + 1) * 3367900313u;
            unsigned int h1a = (unsigned int)iy * 2654435761u;
            unsigned int h1b = (unsigned int)(iy + 1) * 2654435761u;
            unsigned int h2a = (unsigned int)iz * 805459861u;
            unsigned int h2b = (unsigned int)(iz + 1) * 805459861u;
            unsigned int idx[8];
            idx[0] = (h0a ^ h1a ^ h2a) & HASH_MASK;
            idx[1] = (h0a ^ h1a ^ h2b) & HASH_MASK;
            idx[2] = (h0a ^ h1b ^ h2a) & HASH_MASK;
            idx[3] = (h0a ^ h1b ^ h2b) & HASH_MASK;
            idx[4] = (h0b ^ h1a ^ h2a) & HASH_MASK;
            idx[5] = (h0b ^ h1a ^ h2b) & HASH_MASK;
            idx[6] = (h0b ^ h1b ^ h2a) & HASH_MASK;
            idx[7] = (h0b ^ h1b ^ h2b) & HASH_MASK;
            float wxa[2] = {mxw, xw};
            float wya[2] = {myw, yw};
            float wza[2] = {mzw, zw};
#pragma unroll
            for (int c = 0; c < 8; ++c) {
                float w = wxa[(c >> 2) & 1] * wya[(c >> 1) & 1] * wza[c & 1];
                float2 v = __ldg(&t[idx[c]]);
                accx = fmaf(w, v.x, accx);
                accy = fmaf(w, v.y, accy);
            }
        }
        my[2 * l + 0] = accx;
        my[2 * l + 1] = accy;
    }

    __syncwarp();
    int warp = tid >> 5, lane = tid & 31;
    long long warpbase = (long long)blockIdx.x * 256 + warp * 32;
    const float* ws = srow + (warp * 32) * 33;
#pragma unroll 1
    for (int p2 = 0; p2 < 32; ++p2) {
        long long pt = warpbase + p2;
        if (pt < n) out[pt * 32 + lane] = ws[p2 * 33 + lane];
    }
}

// ---------------------------------------------------------------------------
// Levels 0 + 1 via shared-memory tables (16^3 + 22^3 entries = 118 KB).
// Writes cols 0..3 of each output row (one float4).
// ---------------------------------------------------------------------------
#define L0_ENT 4096    // 16^3
#define L1_ENT 10648   // 22^3

__device__ __forceinline__ float2 dense_lookup_smem(
    const float2* __restrict__ s, float px, float py, float pz,
    float scale, float cap, int res, int res2)
{
    float cx = fminf(fmaxf(px * scale, 0.0f), cap);
    float cy = fminf(fmaxf(py * scale, 0.0f), cap);
    float cz = fminf(fmaxf(pz * scale, 0.0f), cap);
    float fx = floorf(cx), fy = floorf(cy), fz = floorf(cz);
    int ix = (int)fx, iy = (int)fy, iz = (int)fz;
    float xw = cx - fx, yw = cy - fy, zw = cz - fz;
    float mxw = 1.0f - xw, myw = 1.0f - yw, mzw = 1.0f - zw;

    int base = ix + iy * res + iz * res2;
    float wyz[4] = {myw * mzw, myw * zw, yw * mzw, yw * zw};
    int offs[4] = {0, res2, res, res + res2};
    float accx = 0.0f, accy = 0.0f;
#pragma unroll
    for (int r = 0; r < 4; ++r) {
        int u = base + offs[r];
        float2 e0 = s[u];
        float2 e1 = s[u + 1];
        float w0 = wyz[r] * mxw, w1 = wyz[r] * xw;
        accx = fmaf(w0, e0.x, fmaf(w1, e1.x, accx));
        accy = fmaf(w0, e0.y, fmaf(w1, e1.y, accy));
    }
    return make_float2(accx, accy);
}

__global__ __launch_bounds__(512)
void grid_lvl01_kernel(const float* __restrict__ x,
                       const float* __restrict__ tables,
                       float* __restrict__ out,
                       int n)
{
    extern __shared__ float2 sm2[];   // [L0_ENT + L1_ENT]
    const float2* t0g = (const float2*)tables;                       // level 0
    const float2* t1g = (const float2*)(tables + 2 * MAX_ENTRY);     // level 1
    for (int j = threadIdx.x; j < L0_ENT; j += 512) sm2[j] = __ldg(&t0g[j]);
    for (int j = threadIdx.x; j < L1_ENT; j += 512) sm2[L0_ENT + j] = __ldg(&t1g[j]);
    __syncthreads();

    int per = (n + gridDim.x - 1) / gridDim.x;
    int start = blockIdx.x * per;
    int end = min(start + per, n);

    const float2* s0 = sm2;
    const float2* s1 = sm2 + L0_ENT;
    const float cap0 = (float)(16.0 - 1.0001);
    const float cap1 = (float)(22.0 - 1.0001);

    for (int i = start + (int)threadIdx.x; i < end; i += 512) {
        float px = __ldg(&x[3 * i + 0]);
        float py = __ldg(&x[3 * i + 1]);
        float pz = __ldg(&x[3 * i + 2]);
        float2 f0 = dense_lookup_smem(s0, px, py, pz, 15.0f, cap0, 16, 256);
        float2 f1 = dense_lookup_smem(s1, px, py, pz, 21.0f, cap1, 22, 484);
        float4 o = make_float4(f0.x, f0.y, f1.x, f1.y);
        ((float4*)out)[(size_t)i * 8] = o;   // cols 0..3
    }
}

// ---------------------------------------------------------------------------
// Level 2 via shared-memory table (30^3 entries = 211 KB).
// Writes cols 4..5 of each output row (one float2).
// ---------------------------------------------------------------------------
#define L2_ENT 27000   // 30^3

__global__ __launch_bounds__(512)
void grid_lvl2_kernel(const float* __restrict__ x,
                      const float* __restrict__ tables,
                      float* __restrict__ out,
                      int n)
{
    extern __shared__ float2 sm2[];   // [L2_ENT]
    const float2* t2g = (const float2*)(tables + 2 * (size_t)MAX_ENTRY * 2);  // level 2
    for (int j = threadIdx.x; j < L2_ENT; j += 512) sm2[j] = __ldg(&t2g[j]);
    __syncthreads();

    int per = (n + gridDim.x - 1) / gridDim.x;
    int start = blockIdx.x * per;
    int end = min(start + per, n);
    const float cap2 = (float)(30.0 - 1.0001);

    for (int i = start + (int)threadIdx.x; i < end; i += 512) {
        float px = __ldg(&x[3 * i + 0]);
        float py = __ldg(&x[3 * i + 1]);
        float pz = __ldg(&x[3 * i + 2]);
        float2 f2 = dense_lookup_smem(sm2, px, py, pz, 29.0f, cap2, 30, 900);
        ((float2*)out)[(size_t)i * 16 + 2] = f2;   // cols 4..5
    }
}

extern "C" void kernel_launch(void* const* d_in, const int* in_sizes, int n_in,
                              void* d_out, int out_size) {
    const float* x      = (const float*)d_in[0];   // (N, 3) f32
    const float* tables = (const float*)d_in[1];   // (16, 2^19, 2) f32
    float* out = (float*)d_out;                    // (N, 32) f32

    int n = in_sizes[0] / 3;

    // Idempotent; executes immediately (not a stream op). First (non-capture)
    // correctness call establishes the attributes for all later replays.
    cudaFuncSetAttribute(grid_lvl01_kernel,
                         cudaFuncAttributeMaxDynamicSharedMemorySize,
                         (L0_ENT + L1_ENT) * (int)sizeof(float2));
    cudaFuncSetAttribute(grid_lvl2_kernel,
                         cudaFuncAttributeMaxDynamicSharedMemorySize,
                         L2_ENT * (int)sizeof(float2));

    init_lvl_kernel<<<1, 32>>>();

    int blocks = (n + 255) / 256;
    grid_main_kernel<<<blocks, 256>>>(x, tables, out, n);   // writes full rows (0..5 zero)
    grid_lvl01_kernel<<<148, 512, (L0_ENT + L1_ENT) * sizeof(float2)>>>(x, tables, out, n);
    grid_lvl2_kernel<<<148, 512, L2_ENT * sizeof(float2)>>>(x, tables, out, n);
}

// round 3
// speedup vs baseline: 1.4732x; 1.4732x over previous
#include <cuda_runtime.h>
#include <math.h>
#include <stdint.h>

#define NLVL 16
#define MAX_ENTRY (1u << 19)
#define HASH_MASK (MAX_ENTRY - 1u)

#define L0_ENT 4096    // 16^3
#define L1_ENT 10648   // 22^3
#define SMEM_BYTES ((L0_ENT + L1_ENT) * 8)

// Per-level parameters, computed on device to bit-match numpy's double math.
struct LvlP {
    float scale;   // res - 1.0
    float cap;     // (float)(res - 1.0001)
    int   res;
    int   res2;
    int   dense;   // 1 if res^3 < 2^19
};

__device__ LvlP g_lvl[NLVL];

__global__ void init_lvl_kernel() {
    int l = threadIdx.x;
    if (l < NLVL) {
        double step = (log(2048.0) - log(16.0)) / 15.0;
        double b = exp(step);
        double r = floor(16.0 * pow(b, (double)l));
        LvlP p;
        int res = (int)r;
        p.scale = (float)(r - 1.0);
        p.cap   = (float)(r - 1.0001);
        p.res   = res;
        p.res2  = res * res;
        p.dense = ((r * r * r) < (double)MAX_ENTRY) ? 1 : 0;
        g_lvl[l] = p;
    }
}

__device__ __forceinline__ float2 dense_lookup_smem(
    const float2* __restrict__ s, float px, float py, float pz,
    float scale, float cap, int res, int res2)
{
    float cx = fminf(fmaxf(px * scale, 0.0f), cap);
    float cy = fminf(fmaxf(py * scale, 0.0f), cap);
    float cz = fminf(fmaxf(pz * scale, 0.0f), cap);
    float fx = floorf(cx), fy = floorf(cy), fz = floorf(cz);
    int ix = (int)fx, iy = (int)fy, iz = (int)fz;
    float xw = cx - fx, yw = cy - fy, zw = cz - fz;
    float mxw = 1.0f - xw, myw = 1.0f - yw, mzw = 1.0f - zw;

    int base = ix + iy * res + iz * res2;
    float wyz[4] = {myw * mzw, myw * zw, yw * mzw, yw * zw};
    int offs[4] = {0, res2, res, res + res2};
    float accx = 0.0f, accy = 0.0f;
#pragma unroll
    for (int r = 0; r < 4; ++r) {
        int u = base + offs[r];
        float2 e0 = s[u];
        float2 e1 = s[u + 1];
        float w0 = wyz[r] * mxw, w1 = wyz[r] * xw;
        accx = fmaf(w0, e0.x, fmaf(w1, e1.x, accx));
        accy = fmaf(w0, e0.y, fmaf(w1, e1.y, accy));
    }
    return make_float2(accx, accy);
}

// ---------------------------------------------------------------------------
// One fused persistent kernel:
//   levels 0,1 : shared-memory tables (118 KB), LDS gathers
//   levels 2-15: R1-style LDG gathers (dense linear or xor-prime hash)
// ---------------------------------------------------------------------------
__global__ __launch_bounds__(1024, 1)
void grid_all_kernel(const float* __restrict__ x,
                     const float* __restrict__ tables,
                     float* __restrict__ out,
                     int n)
{
    extern __shared__ float2 sm[];   // [L0_ENT + L1_ENT]

    // Cooperative table load (vectorized float4 = 2 entries per load)
    {
        float4* sv = (float4*)sm;
        const float4* t0 = (const float4*)tables;                       // level 0
        const float4* t1 = (const float4*)(tables + 2 * (size_t)MAX_ENTRY);  // level 1
        for (int j = threadIdx.x; j < L0_ENT / 2; j += 1024)
            sv[j] = __ldg(&t0[j]);
        for (int j = threadIdx.x; j < L1_ENT / 2; j += 1024)
            sv[L0_ENT / 2 + j] = __ldg(&t1[j]);
    }
    __syncthreads();

    const float2* __restrict__ s0 = sm;
    const float2* __restrict__ s1 = sm + L0_ENT;
    const float2* __restrict__ tbl = (const float2*)tables;

    const float cap0 = (float)(16.0 - 1.0001);
    const float cap1 = (float)(22.0 - 1.0001);

    int stride = gridDim.x * 1024;
    for (int i = blockIdx.x * 1024 + (int)threadIdx.x; i < n; i += stride) {
        float px = __ldg(&x[3 * i + 0]);
        float py = __ldg(&x[3 * i + 1]);
        float pz = __ldg(&x[3 * i + 2]);

        float res_out[2 * NLVL];

        // Levels 0,1 from shared memory
        float2 f0 = dense_lookup_smem(s0, px, py, pz, 15.0f, cap0, 16, 256);
        res_out[0] = f0.x; res_out[1] = f0.y;
        float2 f1 = dense_lookup_smem(s1, px, py, pz, 21.0f, cap1, 22, 484);
        res_out[2] = f1.x; res_out[3] = f1.y;

        // Levels 2..15 from global (R1-proven body)
#pragma unroll 1
        for (int l = 2; l < NLVL; ++l) {
            LvlP p = g_lvl[l];

            float cx = fminf(fmaxf(px * p.scale, 0.0f), p.cap);
            float cy = fminf(fmaxf(py * p.scale, 0.0f), p.cap);
            float cz = fminf(fmaxf(pz * p.scale, 0.0f), p.cap);
            float fx = floorf(cx), fy = floorf(cy), fz = floorf(cz);
            int ix = (int)fx, iy = (int)fy, iz = (int)fz;

            float xw = cx - fx, yw = cy - fy, zw = cz - fz;
            float wxa[2] = {1.0f - xw, xw};
            float wya[2] = {1.0f - yw, yw};
            float wza[2] = {1.0f - zw, zw};

            unsigned int idx[8];
            if (p.dense) {
                unsigned int base = (unsigned int)(ix + iy * p.res + iz * p.res2);
                unsigned int dr = (unsigned int)p.res;
                unsigned int dr2 = (unsigned int)p.res2;
                idx[0] = base;
                idx[1] = base + dr2;
                idx[2] = base + dr;
                idx[3] = base + dr + dr2;
                idx[4] = base + 1u;
                idx[5] = base + 1u + dr2;
                idx[6] = base + 1u + dr;
                idx[7] = base + 1u + dr + dr2;
            } else {
                unsigned int h0a = (unsigned int)ix * 3367900313u;
                unsigned int h0b = (unsigned int)(ix + 1) * 3367900313u;
                unsigned int h1a = (unsigned int)iy * 2654435761u;
                unsigned int h1b = (unsigned int)(iy + 1) * 2654435761u;
                unsigned int h2a = (unsigned int)iz * 805459861u;
                unsigned int h2b = (unsigned int)(iz + 1) * 805459861u;
                idx[0] = (h0a ^ h1a ^ h2a) & HASH_MASK;
                idx[1] = (h0a ^ h1a ^ h2b) & HASH_MASK;
                idx[2] = (h0a ^ h1b ^ h2a) & HASH_MASK;
                idx[3] = (h0a ^ h1b ^ h2b) & HASH_MASK;
                idx[4] = (h0b ^ h1a ^ h2a) & HASH_MASK;
                idx[5] = (h0b ^ h1a ^ h2b) & HASH_MASK;
                idx[6] = (h0b ^ h1b ^ h2a) & HASH_MASK;
                idx[7] = (h0b ^ h1b ^ h2b) & HASH_MASK;
            }

            const float2* __restrict__ t = tbl + (size_t)l * MAX_ENTRY;

            float accx = 0.0f, accy = 0.0f;
#pragma unroll
            for (int c = 0; c < 8; ++c) {
                float w = wxa[(c >> 2) & 1] * wya[(c >> 1) & 1] * wza[c & 1];
                float2 v = __ldg(&t[idx[c]]);
                accx = fmaf(w, v.x, accx);
                accy = fmaf(w, v.y, accy);
            }
            res_out[2 * l + 0] = accx;
            res_out[2 * l + 1] = accy;
        }

        // 128B-per-thread output: 8 x float4 (R1-proven)
        float4* o = (float4*)(out + (size_t)i * (2 * NLVL));
#pragma unroll
        for (int k = 0; k < 8; ++k) {
            o[k] = ((const float4*)res_out)[k];
        }
    }
}

extern "C" void kernel_launch(void* const* d_in, const int* in_sizes, int n_in,
                              void* d_out, int out_size) {
    const float* x      = (const float*)d_in[0];   // (N, 3) f32
    const float* tables = (const float*)d_in[1];   // (16, 2^19, 2) f32
    float* out = (float*)d_out;                    // (N, 32) f32

    int n = in_sizes[0] / 3;

    cudaFuncSetAttribute(grid_all_kernel,
                         cudaFuncAttributeMaxDynamicSharedMemorySize,
                         SMEM_BYTES);

    init_lvl_kernel<<<1, 32>>>();

    int blocks = 148;   // 1 persistent block per SM (118 KB smem each)
    grid_all_kernel<<<blocks, 1024, SMEM_BYTES>>>(x, tables, out, n);
}